// round 1
// baseline (speedup 1.0000x reference)
#include <cuda_runtime.h>

#define LDD 192
#define M_TOTAL 64000

// ---------------- scratch (static device globals; no allocation) ----------------
static __device__ float g_A[(size_t)M_TOTAL * LDD];   // 49 MB
static __device__ float g_B[(size_t)M_TOTAL * LDD];   // 49 MB
static __device__ float g_G[LDD * LDD];
static __device__ float g_T[LDD * LDD];
static __device__ float g_S[LDD * LDD];
static __device__ float g_P[LDD * LDD];
static __device__ float g_Wp[LDD * LDD];

// ---------------- per-branch compile-time traits ----------------
template<int BR> struct Tr;
template<> struct Tr<0> { // axi: s=(48,66,38) ps=(50,70,40) w=(5,7,4) d=140 pb=(1,2,1)
  static constexpr int w0=5,w1=7,w2=4,d=140;
  static constexpr int s0=48,s1=66,s2=38;
  static constexpr int pb0=1,pb1=2,pb2=1;
  static constexpr long OFF=0;
};
template<> struct Tr<1> { // cor (internal = cor.transpose(0,1,2,4,3)): s=(38,38,66) w=(4,4,7) d=112 pb=(1,1,2)
  static constexpr int w0=4,w1=4,w2=7,d=112;
  static constexpr int s0=38,s1=38,s2=66;
  static constexpr int pb0=1,pb1=1,pb2=2;
  static constexpr long OFF=7704576;   // after axi (64*48*66*38)
};
template<> struct Tr<2> { // sag (internal = sag.transpose(0,1,4,3,2)): s=(38,78,48) w=(4,8,5) d=160 pb=(1,1,1)
  static constexpr int w0=4,w1=8,w2=5,d=160;
  static constexpr int s0=38,s1=78,s2=48;
  static constexpr int pb0=1,pb1=1,pb2=1;
  static constexpr long OFF=13804032;  // after axi+cor (+64*38*66*38)
};

// composed nearest-resample chain: branch (x,y,z) -> base atlas (5,6,4) coords
template<int BR>
__device__ __forceinline__ void amap(int x, int y, int z, int& xb, int& yb, int& zb) {
  if (BR == 0) {            // (5,6,4) -> (5,7,4)
    xb = x; yb = (y * 6) / 7; zb = z;
  } else if (BR == 1) {     // -> (5,7,4) -> (4,4,7)
    int x2 = (x * 5) / 4, y2 = (y * 7) / 4, z2 = (z * 4) / 7;
    xb = x2; yb = (y2 * 6) / 7; zb = z2;
  } else {                  // -> (4,4,7) -> (4,8,5)
    int y3 = y / 2, z3 = (z * 7) / 5;
    int x2 = (x * 5) / 4, y2 = (y3 * 7) / 4, z2 = (z3 * 4) / 7;
    xb = x2; yb = (y2 * 6) / 7; zb = z2;
  }
}

// ---------------- pack: gather A-hat and B-hat (ones column at j==d, zeros beyond) ----------------
template<int BR>
__global__ void pack_kernel(const float* __restrict__ feat, const float* __restrict__ atlas) {
  constexpr int w0=Tr<BR>::w0, w1=Tr<BR>::w1, w2=Tr<BR>::w2, d=Tr<BR>::d;
  constexpr int s0=Tr<BR>::s0, s1=Tr<BR>::s1, s2=Tr<BR>::s2;
  constexpr int pb0=Tr<BR>::pb0, pb1=Tr<BR>::pb1, pb2=Tr<BR>::pb2;
  int blk = blockIdx.x;              // (c*10 + a)*10 + b
  int c = blk / 100;
  int a = (blk / 10) % 10;
  int b = blk % 10;
  for (int t = threadIdx.x; t < 10 * LDD; t += blockDim.x) {
    int cc = t / LDD;
    int j  = t - cc * LDD;
    int row = blk * 10 + cc;
    float vB, vA;
    if (j < d) {
      int x = j / (w1 * w2);
      int y = (j / w2) % w1;
      int z = j % w2;
      // ---- B gather (padded-unfold of feat, with branch transpose folded in) ----
      int i0 = a * w0 + x - pb0;
      int i1 = b * w1 + y - pb1;
      int i2 = cc * w2 + z - pb2;
      vB = 0.f;
      if ((unsigned)i0 < (unsigned)s0 && (unsigned)i1 < (unsigned)s1 && (unsigned)i2 < (unsigned)s2) {
        int src;
        if (BR == 0)      src = ((c * 48 + i0) * 66 + i1) * 38 + i2;
        else if (BR == 1) src = ((c * 38 + i0) * 66 + i2) * 38 + i1;  // cor[c][i0][i2][i1]
        else              src = ((c * 48 + i2) * 78 + i1) * 38 + i0;  // sag[c][i2][i1][i0]
        vB = feat[src];
      }
      // ---- A gather (atlas padded-unfold + composed nearest resample chain) ----
      int xb, yb, zb;
      amap<BR>(x, y, z, xb, yb, zb);
      int j0 = a * 5 + xb - 2;   // atlas aw=(5,6,4), pb=(2,2,1)
      int j1 = b * 6 + yb - 2;
      int j2 = cc * 4 + zb - 1;
      vA = 0.f;
      if ((unsigned)j0 < 46u && (unsigned)j1 < 56u && (unsigned)j2 < 38u)
        vA = atlas[((c * 46 + j0) * 56 + j1) * 38 + j2];
    } else {
      vB = (j == d) ? 1.f : 0.f;   // augmented ones column; zero pad beyond
      vA = vB;
    }
    g_B[row * LDD + j] = vB;
    g_A[row * LDD + j] = vA;
  }
}

__global__ void zero_G_kernel() {
  int i = blockIdx.x * blockDim.x + threadIdx.x;
  if (i < LDD * LDD) g_G[i] = 0.f;
}

// ---------------- GEMM1: G = A-hat^T * B-hat, split-K over m with atomic reduce ----------------
__global__ void gemm1_kernel(int mChunk) {
  int p0 = blockIdx.x * 64;
  int q0 = blockIdx.y * 64;
  int m0 = blockIdx.z * mChunk;
  int mHi = min(m0 + mChunk, M_TOTAL);
  __shared__ float As[16][64];
  __shared__ float Bs[16][64];
  float acc[4][4] = {};
  int tx = threadIdx.x & 15;
  int ty = threadIdx.x >> 4;
  int lk = threadIdx.x >> 4;         // 0..15 (k row in chunk)
  int lc = (threadIdx.x & 15) * 4;   // col group
  for (int mb = m0; mb < mHi; mb += 16) {
    int mrow = mb + lk;
    float4 a4 = make_float4(0.f, 0.f, 0.f, 0.f);
    float4 b4 = make_float4(0.f, 0.f, 0.f, 0.f);
    if (mrow < mHi) {
      a4 = *(const float4*)(g_A + mrow * LDD + p0 + lc);
      b4 = *(const float4*)(g_B + mrow * LDD + q0 + lc);
    }
    __syncthreads();
    *(float4*)&As[lk][lc] = a4;
    *(float4*)&Bs[lk][lc] = b4;
    __syncthreads();
#pragma unroll
    for (int k = 0; k < 16; k++) {
      float4 av = *(float4*)&As[k][ty * 4];
      float4 bv = *(float4*)&Bs[k][tx * 4];
      float aa[4] = {av.x, av.y, av.z, av.w};
      float bb[4] = {bv.x, bv.y, bv.z, bv.w};
#pragma unroll
      for (int i = 0; i < 4; i++)
#pragma unroll
        for (int jj = 0; jj < 4; jj++)
          acc[i][jj] += aa[i] * bb[jj];
    }
  }
#pragma unroll
  for (int i = 0; i < 4; i++)
#pragma unroll
    for (int jj = 0; jj < 4; jj++)
      atomicAdd(&g_G[(p0 + ty * 4 + i) * LDD + (q0 + tx * 4 + jj)], acc[i][jj]);
}

// ---------------- small GEMMs: S = Wq-hat^T * G-hat * Wk-hat ----------------
// T = G-hat @ Wk-hat   (D x d), Wk-hat[s][q] = s<d ? Wk[s][q] : bk[q]
__global__ void k3a_kernel(const float* __restrict__ Wk, const float* __restrict__ bk, int d) {
  int q = blockIdx.x * 16 + threadIdx.x;
  int r = blockIdx.y * 16 + threadIdx.y;
  int D = d + 1;
  if (q >= d || r >= D) return;
  float s = 0.f;
  for (int ss = 0; ss < D; ss++) {
    float wv = (ss < d) ? Wk[ss * d + q] : bk[q];
    s += g_G[r * LDD + ss] * wv;
  }
  g_T[r * LDD + q] = s;
}

// S = Wq-hat^T @ T    (d x d)
__global__ void k3b_kernel(const float* __restrict__ Wq, const float* __restrict__ bq, int d) {
  int q = blockIdx.x * 16 + threadIdx.x;
  int p = blockIdx.y * 16 + threadIdx.y;
  if (q >= d || p >= d) return;
  int D = d + 1;
  float s = 0.f;
  for (int r = 0; r < D; r++) {
    float wv = (r < d) ? Wq[r * d + p] : bq[p];
    s += wv * g_T[r * LDD + q];
  }
  g_S[p * LDD + q] = s;
}

// row softmax of S -> P
__global__ void softmax_kernel(int d) {
  int p = blockIdx.x;
  __shared__ float red[256];
  int t = threadIdx.x;
  float mx = -1e30f;
  for (int q = t; q < d; q += 256) mx = fmaxf(mx, g_S[p * LDD + q]);
  red[t] = mx; __syncthreads();
  for (int s = 128; s > 0; s >>= 1) { if (t < s) red[t] = fmaxf(red[t], red[t + s]); __syncthreads(); }
  mx = red[0]; __syncthreads();
  float sum = 0.f;
  for (int q = t; q < d; q += 256) {
    float e = expf(g_S[p * LDD + q] - mx);
    g_P[p * LDD + q] = e;
    sum += e;
  }
  red[t] = sum; __syncthreads();
  for (int s = 128; s > 0; s >>= 1) { if (t < s) red[t] += red[t + s]; __syncthreads(); }
  float inv = 1.f / red[0];
  for (int q = t; q < d; q += 256) g_P[p * LDD + q] *= inv;
}

// W' = Wv-hat @ P^T  ((d+1) x d), zero-padded to full 192x192
__global__ void k3d_kernel(const float* __restrict__ Wv, const float* __restrict__ bv, int d) {
  int i = blockIdx.x * 16 + threadIdx.x;   // output column (attn row index)
  int j = blockIdx.y * 16 + threadIdx.y;   // Wv-hat row
  float s = 0.f;
  if (j <= d && i < d) {
    for (int l = 0; l < d; l++) {
      float wv = (j < d) ? Wv[j * d + l] : bv[l];
      s += wv * g_P[i * LDD + l];
    }
  }
  g_Wp[j * LDD + i] = s;
}

// ---------------- GEMM2: cross = B-hat @ W', fused fold/crop/transpose scatter ----------------
template<int BR>
__global__ void gemm2_kernel(float* __restrict__ out) {
  constexpr int d  = Tr<BR>::d;
  constexpr int w0 = Tr<BR>::w0, w1 = Tr<BR>::w1, w2 = Tr<BR>::w2;
  constexpr int s0 = Tr<BR>::s0, s1 = Tr<BR>::s1, s2 = Tr<BR>::s2;
  constexpr int pb0 = Tr<BR>::pb0, pb1 = Tr<BR>::pb1, pb2 = Tr<BR>::pb2;
  constexpr int KK = ((d + 1 + 15) / 16) * 16;
  int m0 = blockIdx.x * 64;
  int n0 = blockIdx.y * 64;
  __shared__ float Bs[16][64];   // transposed: Bs[k][row]
  __shared__ float Ws[16][64];
  float acc[4][4] = {};
  int tx = threadIdx.x & 15;
  int ty = threadIdx.x >> 4;
  int brow = threadIdx.x >> 2;          // 0..63
  int bkg  = (threadIdx.x & 3) * 4;     // 0,4,8,12
  int lk = threadIdx.x >> 4;
  int lc = (threadIdx.x & 15) * 4;
  for (int k0 = 0; k0 < KK; k0 += 16) {
    float4 b4 = *(const float4*)(g_B + (m0 + brow) * LDD + k0 + bkg);
    float4 w4 = *(const float4*)(g_Wp + (k0 + lk) * LDD + n0 + lc);
    __syncthreads();
    Bs[bkg + 0][brow] = b4.x;
    Bs[bkg + 1][brow] = b4.y;
    Bs[bkg + 2][brow] = b4.z;
    Bs[bkg + 3][brow] = b4.w;
    *(float4*)&Ws[lk][lc] = w4;
    __syncthreads();
#pragma unroll
    for (int k = 0; k < 16; k++) {
      float4 av = *(float4*)&Bs[k][ty * 4];
      float4 wv = *(float4*)&Ws[k][tx * 4];
      float aa[4] = {av.x, av.y, av.z, av.w};
      float bb[4] = {wv.x, wv.y, wv.z, wv.w};
#pragma unroll
      for (int i = 0; i < 4; i++)
#pragma unroll
        for (int jj = 0; jj < 4; jj++)
          acc[i][jj] += aa[i] * bb[jj];
    }
  }
  // epilogue: fold + crop + branch transpose, direct to output
#pragma unroll
  for (int i = 0; i < 4; i++) {
    int m = m0 + ty * 4 + i;
    int c  = m / 1000;
    int rem = m - c * 1000;
    int a  = rem / 100;
    int b  = (rem / 10) % 10;
    int cc = rem % 10;
#pragma unroll
    for (int jj = 0; jj < 4; jj++) {
      int col = n0 + tx * 4 + jj;
      if (col < d) {
        int x = col / (w1 * w2);
        int y = (col / w2) % w1;
        int z = col % w2;
        int u0 = a * w0 + x - pb0;
        int u1 = b * w1 + y - pb1;
        int u2 = cc * w2 + z - pb2;
        if ((unsigned)u0 < (unsigned)s0 && (unsigned)u1 < (unsigned)s1 && (unsigned)u2 < (unsigned)s2) {
          long dst;
          if (BR == 0)      dst = ((long)(c * 48 + u0) * 66 + u1) * 38 + u2;
          else if (BR == 1) dst = ((long)(c * 38 + u0) * 66 + u2) * 38 + u1;  // fc -> feat_cor transpose
          else              dst = ((long)(c * 48 + u2) * 78 + u1) * 38 + u0;  // fs -> feat_sag transpose
          out[Tr<BR>::OFF + dst] = acc[i][jj];
        }
      }
    }
  }
}

// ---------------- host-side branch driver ----------------
template<int BR>
static void run_branch(const float* feat, const float* atlas,
                       const float* Wq, const float* bq,
                       const float* Wk, const float* bk,
                       const float* Wv, const float* bv,
                       float* out) {
  constexpr int d  = Tr<BR>::d;
  constexpr int D  = d + 1;
  constexpr int NT = (D + 63) / 64;
  constexpr int NS = (296 + NT * NT - 1) / (NT * NT);
  constexpr int CHUNK = (M_TOTAL + NS - 1) / NS;
  pack_kernel<BR><<<6400, 256>>>(feat, atlas);
  zero_G_kernel<<<(LDD * LDD + 255) / 256, 256>>>();
  gemm1_kernel<<<dim3(NT, NT, NS), 256>>>(CHUNK);
  dim3 tb(16, 16);
  k3a_kernel<<<dim3((d + 15) / 16, (D + 15) / 16), tb>>>(Wk, bk, d);
  k3b_kernel<<<dim3((d + 15) / 16, (d + 15) / 16), tb>>>(Wq, bq, d);
  softmax_kernel<<<d, 256>>>(d);
  k3d_kernel<<<dim3(LDD / 16, LDD / 16), tb>>>(Wv, bv, d);
  gemm2_kernel<BR><<<dim3(1000, NT), 256>>>(out);
}

extern "C" void kernel_launch(void* const* d_in, const int* in_sizes, int n_in,
                              void* d_out, int out_size) {
  const float* axi   = (const float*)d_in[0];
  const float* cor   = (const float*)d_in[1];
  const float* sag   = (const float*)d_in[2];
  const float* atlas = (const float*)d_in[3];
  float* out = (float*)d_out;
  run_branch<0>(axi, atlas,
                (const float*)d_in[4],  (const float*)d_in[5],
                (const float*)d_in[6],  (const float*)d_in[7],
                (const float*)d_in[8],  (const float*)d_in[9], out);
  run_branch<1>(cor, atlas,
                (const float*)d_in[10], (const float*)d_in[11],
                (const float*)d_in[12], (const float*)d_in[13],
                (const float*)d_in[14], (const float*)d_in[15], out);
  run_branch<2>(sag, atlas,
                (const float*)d_in[16], (const float*)d_in[17],
                (const float*)d_in[18], (const float*)d_in[19],
                (const float*)d_in[20], (const float*)d_in[21], out);
}